// round 1
// baseline (speedup 1.0000x reference)
#include <cuda_runtime.h>
#include <cuda_bf16.h>

#define CH    512
#define HWSZ  4096
#define NNODE 20
#define CI_T  8
#define CO_T  64
#define R_T   8
#define C_T   16
#define SIN_STRIDE 21   // 18 needed, 21 to dodge bank conflicts
#define MAXROUND 19

// ------------------------- device globals (scratch) -------------------------
__device__ float g_V1[CH * HWSZ];                   // conv1x1(vis) (no bias)
__device__ float g_A[3][CH * HWSZ];                 // conv3(V1, w_firsthalf) r/u/o
__device__ float g_lb[NNODE][CH];                   // per-node channel constant (incl mconv_b)
__device__ float g_wsum[3][9][CH * CH];             // [w][cls][c*CH+o] tap sums, first half
__device__ float g_bmap[3][NNODE][9 * CH];          // [w][n][cls*CH+o] (incl conv bias)
__device__ float g_wpack[3][2][CH * 9 * CH];        // [w][half][(c*9+k)*CH+o]
__device__ float g_h[NNODE][CH * HWSZ];
__device__ float g_chsum[NNODE][CH * HWSZ];
__device__ float g_rh[NNODE][CH * HWSZ];
__device__ float g_z[NNODE][CH * HWSZ];

__device__ int g_level[NNODE];
__device__ int g_nchild[NNODE];
__device__ int g_child[NNODE][NNODE];
__device__ int g_edgeP[NNODE];
__device__ int g_edgeC[NNODE];
__device__ int g_nedge;
__device__ int g_root;

__device__ __forceinline__ float sigm(float v) { return 1.0f / (1.0f + expf(-v)); }

// ------------------------- tree prep (1 thread) -------------------------
__global__ void k_prep(const int* adj) {
    for (int n = 0; n < NNODE; ++n) g_nchild[n] = 0;
    int ne = 0;
    for (int p = 0; p < NNODE; ++p) {
        for (int c = 0; c < NNODE; ++c) {
            if (adj[p * NNODE + c] > 0) {
                g_child[p][g_nchild[p]++] = c;
                g_edgeP[ne] = p; g_edgeC[ne] = c; ++ne;
            }
        }
    }
    g_nedge = ne;
    for (int n = 0; n < NNODE; ++n) g_level[n] = 0;
    for (int it = 0; it < NNODE; ++it) {
        for (int p = 0; p < NNODE; ++p) {
            if (g_nchild[p] > 0) {
                int m = 0;
                for (int i = 0; i < g_nchild[p]; ++i) {
                    int lv = g_level[g_child[p][i]];
                    if (lv > m) m = lv;
                }
                g_level[p] = m + 1;
            }
        }
    }
    for (int c = 0; c < NNODE; ++c) {
        int cs = 0;
        for (int p = 0; p < NNODE; ++p) cs += adj[p * NNODE + c];
        if (cs == 0) { g_root = c; break; }
    }
}

// ------------------------- lb[n][c] = mconv_b + W_lang . lang_n -------------------------
__global__ void k_lb(const float* lang, const float* mw, const float* mb) {
    int n = blockIdx.x;
    int c = threadIdx.x;
    float acc = mb[c];
    const float* wrow = mw + (size_t)c * 812 + 512;
    const float* lrow = lang + n * 300;
    for (int cl = 0; cl < 300; ++cl) acc += wrow[cl] * lrow[cl];
    g_lb[n][c] = acc;
}

// ------------------------- V1 = conv1x1(vis) : GEMM 512x4096x512 -------------------------
__global__ __launch_bounds__(256) void k_conv1x1(const float* vis, const float* mw) {
    __shared__ float sa[16][64];   // [k][o]
    __shared__ float sb[16][64];   // [k][p]
    int pB = blockIdx.x * 64;
    int oB = blockIdx.y * 64;
    int tid = threadIdx.x;
    int ty = tid >> 4, tx = tid & 15;
    float acc[4][4];
#pragma unroll
    for (int i = 0; i < 4; ++i)
#pragma unroll
        for (int j = 0; j < 4; ++j) acc[i][j] = 0.0f;

    for (int cb = 0; cb < CH; cb += 16) {
        for (int idx = tid; idx < 1024; idx += 256) {
            int k = idx >> 6, o = idx & 63;
            sa[k][o] = mw[(size_t)(oB + o) * 812 + cb + k];
        }
        for (int idx = tid; idx < 1024; idx += 256) {
            int k = idx >> 6, p = idx & 63;
            sb[k][p] = vis[(size_t)(cb + k) * HWSZ + pB + p];
        }
        __syncthreads();
#pragma unroll
        for (int k = 0; k < 16; ++k) {
            float4 a4 = *(const float4*)&sa[k][ty * 4];
            float4 b4 = *(const float4*)&sb[k][tx * 4];
            float av[4] = {a4.x, a4.y, a4.z, a4.w};
            float bv[4] = {b4.x, b4.y, b4.z, b4.w};
#pragma unroll
            for (int i = 0; i < 4; ++i)
#pragma unroll
                for (int j = 0; j < 4; ++j) acc[i][j] += av[i] * bv[j];
        }
        __syncthreads();
    }
#pragma unroll
    for (int i = 0; i < 4; ++i)
#pragma unroll
        for (int j = 0; j < 4; ++j)
            g_V1[(size_t)(oB + ty * 4 + i) * HWSZ + pB + tx * 4 + j] = acc[i][j];
}

// ------------------------- tap-subset sums of first-half weights -------------------------
__global__ void k_wsum(const float* rw, const float* uw, const float* ow) {
    int idx = blockIdx.x * 256 + threadIdx.x;       // 3*512*512 total
    int o = idx & 511;
    int c = (idx >> 9) & 511;
    int w = idx >> 18;
    const float* wp = (w == 0) ? rw : (w == 1) ? uw : ow;
    float t[9];
    const float* base = wp + ((size_t)o * 1024 + c) * 9;
#pragma unroll
    for (int k = 0; k < 9; ++k) t[k] = base[k];
#pragma unroll
    for (int cls = 0; cls < 9; ++cls) {
        int yt = cls / 3, xt = cls % 3;
        int kh0 = (yt == 0) ? 1 : 0, kh1 = (yt == 2) ? 1 : 2;
        int kw0 = (xt == 0) ? 1 : 0, kw1 = (xt == 2) ? 1 : 2;
        float s = 0.0f;
        for (int kh = kh0; kh <= kh1; ++kh)
            for (int kw = kw0; kw <= kw1; ++kw) s += t[kh * 3 + kw];
        g_wsum[w][cls][(size_t)c * CH + o] = s;
    }
}

// ------------------------- bmap[w][n][cls][o] = b_w[o] + lb_n . wsum -------------------------
__global__ __launch_bounds__(256) void k_bmap(const float* rb, const float* ub, const float* ob) {
    __shared__ float lb_s[NNODE * CH];
    int tid = threadIdx.x;
    int o = blockIdx.x * 256 + tid;
    int w = blockIdx.y / 9;
    int cls = blockIdx.y % 9;
    const float* lbf = &g_lb[0][0];
    for (int j = tid; j < NNODE * CH; j += 256) lb_s[j] = lbf[j];
    __syncthreads();
    const float* bptr = (w == 0) ? rb : (w == 1) ? ub : ob;
    float acc[NNODE];
    float bv = bptr[o];
#pragma unroll
    for (int n = 0; n < NNODE; ++n) acc[n] = bv;
    const float* ws = g_wsum[w][cls];
    for (int c = 0; c < CH; ++c) {
        float wv = ws[(size_t)c * CH + o];
#pragma unroll
        for (int n = 0; n < NNODE; ++n) acc[n] += lb_s[n * CH + c] * wv;
    }
#pragma unroll
    for (int n = 0; n < NNODE; ++n) g_bmap[w][n][cls * CH + o] = acc[n];
}

// ------------------------- weight repack to [c][k][o] -------------------------
__global__ void k_pack(const float* rw, const float* uw, const float* ow) {
    long idx = (long)blockIdx.x * 256 + threadIdx.x;
    if (idx >= (long)3 * 2 * CH * 9 * CH) return;
    int o = idx % 512; long t = idx / 512;
    int k = t % 9; t /= 9;
    int c = t % 512; t /= 512;
    int half = t & 1; int w = (int)(t >> 1);
    const float* wp = (w == 0) ? rw : (w == 1) ? uw : ow;
    g_wpack[w][half][((size_t)c * 9 + k) * CH + o] =
        wp[((size_t)o * 1024 + half * 512 + c) * 9 + k];
}

// ------------------------- main conv3x3 (512->512, 64x64), fused epilogues ----------------
// mode 0: A precompute (in=V1, z selects weight, out=g_A[z])
// mode 1: reset conv per edge   mode 2: update conv   mode 3: output conv
__global__ __launch_bounds__(256) void k_conv3(int mode, int round) {
    int bz = blockIdx.z;
    const float* in;
    const float* wp;
    int node = -1;

    if (mode == 0) {
        in = g_V1; wp = g_wpack[bz][0];
    } else if (mode == 1) {
        if (bz >= g_nedge) return;
        node = g_edgeP[bz];
        if (g_level[node] != round) return;
        in = g_h[g_edgeC[bz]]; wp = g_wpack[0][1];
    } else if (mode == 2) {
        node = bz;
        if (g_level[node] != round || g_nchild[node] == 0) return;
        in = g_chsum[node]; wp = g_wpack[1][1];
    } else {
        node = bz;
        if (g_level[node] != round || g_nchild[node] == 0) return;
        in = g_rh[node]; wp = g_wpack[2][1];
    }

    __shared__ float s_in[CI_T * 10 * SIN_STRIDE];
    __shared__ float s_w[CI_T * 9 * CO_T];

    int tid = threadIdx.x;
    int x0 = (blockIdx.x & 3) * C_T;
    int y0 = (blockIdx.x >> 2) * R_T;
    int coBase = blockIdx.y * CO_T;

    int px_grp = tid & 31;
    int co_grp = tid >> 5;
    int row = px_grp >> 2;
    int col0 = (px_grp & 3) << 2;
    int coL = co_grp * 8;

    float acc[8][4];
#pragma unroll
    for (int i = 0; i < 8; ++i)
#pragma unroll
        for (int j = 0; j < 4; ++j) acc[i][j] = 0.0f;

    for (int cb = 0; cb < CH; cb += CI_T) {
        // input patch with halo: [CI_T][10][18]
        for (int idx = tid; idx < CI_T * 10 * 18; idx += 256) {
            int c = idx / 180;
            int rr = (idx / 18) % 10;
            int cc = idx % 18;
            int gy = y0 - 1 + rr;
            int gx = x0 - 1 + cc;
            float v = 0.0f;
            if ((unsigned)gy < 64u && (unsigned)gx < 64u)
                v = in[(size_t)(cb + c) * HWSZ + gy * 64 + gx];
            s_in[c * (10 * SIN_STRIDE) + rr * SIN_STRIDE + cc] = v;
        }
        // weights [c][k][o]
        for (int idx = tid; idx < CI_T * 9 * CO_T; idx += 256) {
            int c = idx / (9 * CO_T);
            int rest = idx % (9 * CO_T);
            int k = rest / CO_T;
            int o = rest % CO_T;
            s_w[idx] = wp[((size_t)(cb + c) * 9 + k) * CH + coBase + o];
        }
        __syncthreads();

#pragma unroll
        for (int c = 0; c < CI_T; ++c) {
            const float* sic = &s_in[c * (10 * SIN_STRIDE)];
#pragma unroll
            for (int kh = 0; kh < 3; ++kh) {
                float win[6];
                const float* rptr = &sic[(row + kh) * SIN_STRIDE + col0];
#pragma unroll
                for (int m = 0; m < 6; ++m) win[m] = rptr[m];
#pragma unroll
                for (int kw = 0; kw < 3; ++kw) {
                    const float* wk = &s_w[(c * 9 + kh * 3 + kw) * CO_T + coL];
                    float4 w0 = *(const float4*)wk;
                    float4 w1 = *(const float4*)(wk + 4);
#pragma unroll
                    for (int j = 0; j < 4; ++j) {
                        float iv = win[kw + j];
                        acc[0][j] += w0.x * iv; acc[1][j] += w0.y * iv;
                        acc[2][j] += w0.z * iv; acc[3][j] += w0.w * iv;
                        acc[4][j] += w1.x * iv; acc[5][j] += w1.y * iv;
                        acc[6][j] += w1.z * iv; acc[7][j] += w1.w * iv;
                    }
                }
            }
        }
        __syncthreads();
    }

    // ---- epilogue ----
    int y = y0 + row;
    int yt = (y == 0) ? 0 : ((y == 63) ? 2 : 1);
    int cls[4], pix[4];
#pragma unroll
    for (int j = 0; j < 4; ++j) {
        int x = x0 + col0 + j;
        int xt = (x == 0) ? 0 : ((x == 63) ? 2 : 1);
        cls[j] = yt * 3 + xt;
        pix[j] = y * 64 + x;
    }

    if (mode == 0) {
        float* outA = g_A[bz];
#pragma unroll
        for (int oo = 0; oo < 8; ++oo) {
            int o = coBase + coL + oo;
#pragma unroll
            for (int j = 0; j < 4; ++j)
                outA[(size_t)o * HWSZ + pix[j]] = acc[oo][j];
        }
    } else if (mode == 1) {
        const float* Ar = g_A[0];
        const float* bm = g_bmap[0][node];
        float* rh = g_rh[node];
#pragma unroll
        for (int oo = 0; oo < 8; ++oo) {
            int o = coBase + coL + oo;
#pragma unroll
            for (int j = 0; j < 4; ++j) {
                size_t idx = (size_t)o * HWSZ + pix[j];
                float r = sigm(acc[oo][j] + Ar[idx] + bm[cls[j] * CH + o]);
                atomicAdd(&rh[idx], r * in[idx]);
            }
        }
    } else if (mode == 2) {
        const float* Au = g_A[1];
        const float* bm = g_bmap[1][node];
        float* zp = g_z[node];
#pragma unroll
        for (int oo = 0; oo < 8; ++oo) {
            int o = coBase + coL + oo;
#pragma unroll
            for (int j = 0; j < 4; ++j) {
                size_t idx = (size_t)o * HWSZ + pix[j];
                zp[idx] = sigm(acc[oo][j] + Au[idx] + bm[cls[j] * CH + o]);
            }
        }
    } else {
        const float* Ao = g_A[2];
        const float* bm = g_bmap[2][node];
        const float* zp = g_z[node];
        const float* cs = g_chsum[node];
        float* hp = g_h[node];
#pragma unroll
        for (int oo = 0; oo < 8; ++oo) {
            int o = coBase + coL + oo;
#pragma unroll
            for (int j = 0; j < 4; ++j) {
                size_t idx = (size_t)o * HWSZ + pix[j];
                float ri = tanhf(acc[oo][j] + Ao[idx] + bm[cls[j] * CH + o]);
                float zz = zp[idx];
                hp[idx] = (1.0f - zz) * ri + zz * cs[idx];
            }
        }
    }
}

// ------------------------- ch_sum + zero reset_hidden -------------------------
__global__ void k_chsum(int round) {
    int n = blockIdx.y;
    if (g_level[n] != round || g_nchild[n] == 0) return;
    int nc = g_nchild[n];
    size_t base = (size_t)blockIdx.x * 2048 + threadIdx.x;
#pragma unroll
    for (int e = 0; e < 8; ++e) {
        size_t i = base + (size_t)e * 256;
        float s = 0.0f;
        for (int ci = 0; ci < nc; ++ci) s += g_h[g_child[n][ci]][i];
        g_chsum[n][i] = s;
        g_rh[n][i] = 0.0f;
    }
}

// ------------------------- leaves: h = (1-z) * tanh(o-field) -------------------------
__global__ void k_leaf() {
    int n = blockIdx.y;
    if (g_nchild[n] != 0) return;
    size_t base = (size_t)blockIdx.x * 2048 + threadIdx.x;
#pragma unroll
    for (int e = 0; e < 8; ++e) {
        size_t i = base + (size_t)e * 256;
        int o = (int)(i >> 12);
        int pixv = (int)(i & 4095);
        int y = pixv >> 6, x = pixv & 63;
        int yt = (y == 0) ? 0 : ((y == 63) ? 2 : 1);
        int xt = (x == 0) ? 0 : ((x == 63) ? 2 : 1);
        int cls = yt * 3 + xt;
        float zu = sigm(g_A[1][i] + g_bmap[1][n][cls * CH + o]);
        float ro = tanhf(g_A[2][i] + g_bmap[2][n][cls * CH + o]);
        g_h[n][i] = (1.0f - zu) * ro;
    }
}

// ------------------------- copy root h to output -------------------------
__global__ void k_copyout(float* out) {
    int root = g_root;
    size_t base = (size_t)blockIdx.x * 1024 + threadIdx.x;
#pragma unroll
    for (int e = 0; e < 4; ++e) {
        size_t i = base + (size_t)e * 256;
        out[i] = g_h[root][i];
    }
}

// ------------------------- launch -------------------------
extern "C" void kernel_launch(void* const* d_in, const int* in_sizes, int n_in,
                              void* d_out, int out_size) {
    const float* vis  = (const float*)d_in[0];
    const float* lang = (const float*)d_in[1];
    const int*   adj  = (const int*)d_in[2];
    const float* mw   = (const float*)d_in[3];
    const float* mb   = (const float*)d_in[4];
    const float* rw   = (const float*)d_in[5];
    const float* rb   = (const float*)d_in[6];
    const float* uw   = (const float*)d_in[7];
    const float* ub   = (const float*)d_in[8];
    const float* ow   = (const float*)d_in[9];
    const float* ob   = (const float*)d_in[10];
    float* out = (float*)d_out;

    k_prep<<<1, 1>>>(adj);
    {
        long tot = (long)3 * 2 * CH * 9 * CH;
        int blocks = (int)((tot + 255) / 256);
        k_pack<<<blocks, 256>>>(rw, uw, ow);
    }
    k_wsum<<<(3 * CH * CH) / 256, 256>>>(rw, uw, ow);
    k_lb<<<NNODE, CH>>>(lang, mw, mb);
    {
        dim3 g(HWSZ / 64, CH / 64);
        k_conv1x1<<<g, 256>>>(vis, mw);
    }
    {
        dim3 g(2, 27);
        k_bmap<<<g, 256>>>(rb, ub, ob);
    }
    {
        dim3 g(32, CH / CO_T, 3);
        k_conv3<<<g, 256>>>(0, 0);      // A_r, A_u, A_o
    }
    {
        dim3 g(1024, NNODE);
        k_leaf<<<g, 256>>>();
    }
    for (int t = 1; t <= MAXROUND; ++t) {
        dim3 gelem(1024, NNODE);
        k_chsum<<<gelem, 256>>>(t);
        dim3 ge(32, CH / CO_T, NNODE);  // edge slots gate internally
        k_conv3<<<ge, 256>>>(1, t);     // reset per edge -> rh (atomic)
        dim3 gn(32, CH / CO_T, NNODE);
        k_conv3<<<gn, 256>>>(2, t);     // update -> z
        k_conv3<<<gn, 256>>>(3, t);     // output -> h
    }
    k_copyout<<<2048, 256>>>(out);
}

// round 3
// speedup vs baseline: 1.9014x; 1.9014x over previous
#include <cuda_runtime.h>
#include <cuda_fp16.h>
#include <cstdint>

#define CH    512
#define NNODE 20
#define PSTR  66
#define BUFSZ (PSTR * PSTR * CH)
#define MAXROUND 19

#define TILE_BYTES 16384                 // 128 rows x 128B (64 fp16)
#define STAGE_BYTES (4 * TILE_BYTES)     // Ah, Al, Bh, Bl
#define CONV_SMEM (2 * STAGE_BYTES + 1024)

// ======================= helpers =======================
__device__ __forceinline__ uint32_t smem_u32(const void* p) {
    uint32_t a;
    asm("{ .reg .u64 t; cvta.to.shared.u64 t, %1; cvt.u32.u64 %0, t; }" : "=r"(a) : "l"(p));
    return a;
}

__device__ __forceinline__ void ldsm_x4(uint32_t* r, uint32_t addr) {
    asm volatile("ldmatrix.sync.aligned.m8n8.x4.shared.b16 {%0,%1,%2,%3}, [%4];"
        : "=r"(r[0]), "=r"(r[1]), "=r"(r[2]), "=r"(r[3]) : "r"(addr));
}

__device__ __forceinline__ void mma16816(float* d, const uint32_t* a, const uint32_t* b) {
    asm volatile("mma.sync.aligned.m16n8k16.row.col.f32.f16.f16.f32 "
        "{%0,%1,%2,%3}, {%4,%5,%6,%7}, {%8,%9}, {%0,%1,%2,%3};"
        : "+f"(d[0]), "+f"(d[1]), "+f"(d[2]), "+f"(d[3])
        : "r"(a[0]), "r"(a[1]), "r"(a[2]), "r"(a[3]), "r"(b[0]), "r"(b[1]));
}

__device__ __forceinline__ void cp_async16(uint32_t saddr, const void* gaddr) {
    asm volatile("cp.async.cg.shared.global [%0], [%1], 16;" :: "r"(saddr), "l"(gaddr) : "memory");
}
#define CP_COMMIT() asm volatile("cp.async.commit_group;" ::: "memory")
#define CP_WAIT0()  asm volatile("cp.async.wait_group 0;" ::: "memory")

__device__ __forceinline__ uint32_t packh2(float x, float y) {
    __half2 h = __floats2half2_rn(x, y);
    return *(uint32_t*)&h;
}
__device__ __forceinline__ void cvt8(float4 a, float4 b, uint4& uh, uint4& ul) {
    float f[8] = {a.x, a.y, a.z, a.w, b.x, b.y, b.z, b.w};
    float l[8];
#pragma unroll
    for (int i = 0; i < 8; ++i) {
        __half h = __float2half_rn(f[i]);
        l[i] = f[i] - __half2float(h);
    }
    uh.x = packh2(f[0], f[1]); uh.y = packh2(f[2], f[3]);
    uh.z = packh2(f[4], f[5]); uh.w = packh2(f[6], f[7]);
    ul.x = packh2(l[0], l[1]); ul.y = packh2(l[2], l[3]);
    ul.z = packh2(l[4], l[5]); ul.w = packh2(l[6], l[7]);
}

__device__ __forceinline__ float sigm(float v) { return 1.0f / (1.0f + expf(-v)); }

// ======================= device globals =======================
__device__ float g_visT[BUFSZ];
__device__ float g_V1[BUFSZ];
__device__ float g_A[3][BUFSZ];
__device__ float g_h[NNODE][BUFSZ];
__device__ float g_chsum[NNODE][BUFSZ];
__device__ float g_rh[NNODE][BUFSZ];
__device__ float g_z[NNODE][BUFSZ];

__device__ __half g_wtc[6][2][9][512][512];   // [w*2+half][split][tap][o][c]
__device__ __half g_mtc[2][512][512];         // mconv vis half [split][o][c]

__device__ float g_lb[NNODE][CH];
__device__ float g_wsum[3][9][CH * CH];
__device__ float g_bmap[3][NNODE][9 * CH];

__device__ int g_level[NNODE];
__device__ int g_nchild[NNODE];
__device__ int g_child[NNODE][NNODE];
__device__ int g_edgeP[NNODE];
__device__ int g_edgeC[NNODE];
__device__ int g_nedge;
__device__ int g_root;

// ======================= tree prep =======================
__global__ void k_prep(const int* adj) {
    for (int n = 0; n < NNODE; ++n) g_nchild[n] = 0;
    int ne = 0;
    for (int p = 0; p < NNODE; ++p)
        for (int c = 0; c < NNODE; ++c)
            if (adj[p * NNODE + c] > 0) {
                g_child[p][g_nchild[p]++] = c;
                g_edgeP[ne] = p; g_edgeC[ne] = c; ++ne;
            }
    g_nedge = ne;
    for (int n = 0; n < NNODE; ++n) g_level[n] = 0;
    for (int it = 0; it < NNODE; ++it)
        for (int p = 0; p < NNODE; ++p)
            if (g_nchild[p] > 0) {
                int m = 0;
                for (int i = 0; i < g_nchild[p]; ++i) {
                    int lv = g_level[g_child[p][i]];
                    if (lv > m) m = lv;
                }
                g_level[p] = m + 1;
            }
    for (int c = 0; c < NNODE; ++c) {
        int cs = 0;
        for (int p = 0; p < NNODE; ++p) cs += adj[p * NNODE + c];
        if (cs == 0) { g_root = c; break; }
    }
}

// ======================= zero borders of all padded buffers =======================
__device__ __forceinline__ float* buf_ptr(int i) {
    if (i == 0) return g_visT;
    if (i == 1) return g_V1;
    if (i < 5) return g_A[i - 2];
    int j = i - 5; int n = j >> 2; int k = j & 3;
    return (k == 0) ? g_h[n] : (k == 1) ? g_chsum[n] : (k == 2) ? g_rh[n] : g_z[n];
}
__global__ void k_zero() {
    float* p = buf_ptr(blockIdx.y);
    int i = blockIdx.x * 256 + threadIdx.x;           // 260 border px * 512 ch
    int c = i & 511; int bi = i >> 9;
    int pp;
    if (bi < 66) pp = bi;
    else if (bi < 132) pp = 65 * PSTR + (bi - 66);
    else { int j = bi - 132; int y = 1 + (j >> 1); int x = (j & 1) * 65; pp = y * PSTR + x; }
    p[(size_t)pp * 512 + c] = 0.0f;
}

// ======================= vis NCHW -> padded NHWC =======================
__global__ __launch_bounds__(256) void k_tvis(const float* vis) {
    __shared__ float sm[64][129];
    int y = blockIdx.x; int cc = blockIdx.y;
    for (int i = threadIdx.x; i < 64 * 128; i += 256) {
        int c = i >> 6, x = i & 63;
        sm[x][c] = vis[(size_t)(cc * 128 + c) * 4096 + y * 64 + x];
    }
    __syncthreads();
    for (int i = threadIdx.x; i < 64 * 128; i += 256) {
        int x = i >> 7, c = i & 127;
        g_visT[(size_t)((y + 1) * PSTR + x + 1) * 512 + cc * 128 + c] = sm[x][c];
    }
}

// ======================= weight packing (fp16 hi/lo, [t][o][c]) =======================
__global__ void k_packtc(const float* rw, const float* uw, const float* ow, const float* mw) {
    size_t idx = (size_t)blockIdx.x * 256 + threadIdx.x;
    const size_t tot = (size_t)6 * 9 * 512 * 512;
    if (idx < tot) {
        int c = idx & 511; size_t r = idx >> 9;
        int o = r & 511; r >>= 9;
        int t = (int)(r % 9); r /= 9;
        int wh = (int)r; int w = wh >> 1, half = wh & 1;
        const float* wp = (w == 0) ? rw : (w == 1) ? uw : ow;
        float v = wp[((size_t)o * 1024 + half * 512 + c) * 9 + t];
        __half hi = __float2half_rn(v);
        float lo = v - __half2float(hi);
        g_wtc[wh][0][t][o][c] = hi;
        g_wtc[wh][1][t][o][c] = __float2half_rn(lo);
    } else if (idx < tot + (size_t)512 * 512) {
        size_t j = idx - tot; int c = (int)(j & 511); int o = (int)(j >> 9);
        float v = mw[(size_t)o * 812 + c];
        __half hi = __float2half_rn(v);
        float lo = v - __half2float(hi);
        g_mtc[0][o][c] = hi;
        g_mtc[1][o][c] = __float2half_rn(lo);
    }
}

// ======================= lb / wsum / bmap =======================
__global__ void k_lb(const float* lang, const float* mw, const float* mb) {
    int n = blockIdx.x; int c = threadIdx.x;
    float acc = mb[c];
    const float* wrow = mw + (size_t)c * 812 + 512;
    const float* lrow = lang + n * 300;
    for (int cl = 0; cl < 300; ++cl) acc += wrow[cl] * lrow[cl];
    g_lb[n][c] = acc;
}

__global__ void k_wsum(const float* rw, const float* uw, const float* ow) {
    int idx = blockIdx.x * 256 + threadIdx.x;
    int o = idx & 511; int c = (idx >> 9) & 511; int w = idx >> 18;
    const float* wp = (w == 0) ? rw : (w == 1) ? uw : ow;
    float t[9];
    const float* base = wp + ((size_t)o * 1024 + c) * 9;
#pragma unroll
    for (int k = 0; k < 9; ++k) t[k] = base[k];
#pragma unroll
    for (int cls = 0; cls < 9; ++cls) {
        int yt = cls / 3, xt = cls % 3;
        int kh0 = (yt == 0) ? 1 : 0, kh1 = (yt == 2) ? 1 : 2;
        int kw0 = (xt == 0) ? 1 : 0, kw1 = (xt == 2) ? 1 : 2;
        float s = 0.0f;
        for (int kh = kh0; kh <= kh1; ++kh)
            for (int kw = kw0; kw <= kw1; ++kw) s += t[kh * 3 + kw];
        g_wsum[w][cls][(size_t)c * CH + o] = s;
    }
}

__global__ __launch_bounds__(256) void k_bmap(const float* rb, const float* ub, const float* ob) {
    __shared__ float lb_s[NNODE * CH];
    int tid = threadIdx.x;
    int o = blockIdx.x * 256 + tid;
    int w = blockIdx.y / 9;
    int cls = blockIdx.y % 9;
    const float* lbf = &g_lb[0][0];
    for (int j = tid; j < NNODE * CH; j += 256) lb_s[j] = lbf[j];
    __syncthreads();
    const float* bptr = (w == 0) ? rb : (w == 1) ? ub : ob;
    float acc[NNODE];
    float bv = bptr[o];
#pragma unroll
    for (int n = 0; n < NNODE; ++n) acc[n] = bv;
    const float* ws = g_wsum[w][cls];
    for (int c = 0; c < CH; ++c) {
        float wv = ws[(size_t)c * CH + o];
#pragma unroll
        for (int n = 0; n < NNODE; ++n) acc[n] += lb_s[n * CH + c] * wv;
    }
#pragma unroll
    for (int n = 0; n < NNODE; ++n) g_bmap[w][n][cls * CH + o] = acc[n];
}

// ======================= tensor-core conv (mma.sync) =======================
// mode 4: V1 = mconv_vis(visT)   (K=512, center tap only)
// mode 0: g_A[bz] = conv3(V1, w[bz] first half)
// mode 12: bz<20: reset per edge -> atomic rh ; bz>=20: update -> z
// mode 3: output conv -> h
__global__ __launch_bounds__(256) void k_conv(int mode, int round) {
    int bz = blockIdx.z;
    const float* in = nullptr;
    const __half* wA0; const __half* wA1;
    int emode, node = -1, outsel = 0;

    if (mode == 4) {
        in = g_visT; wA0 = &g_mtc[0][0][0]; wA1 = &g_mtc[1][0][0]; emode = 4;
    } else if (mode == 0) {
        in = g_V1; int wh = bz * 2;
        wA0 = &g_wtc[wh][0][0][0][0]; wA1 = &g_wtc[wh][1][0][0][0];
        emode = 0; outsel = bz;
    } else if (mode == 12) {
        if (bz < NNODE) {
            if (bz >= g_nedge) return;
            node = g_edgeP[bz];
            if (g_level[node] != round) return;
            in = g_h[g_edgeC[bz]];
            wA0 = &g_wtc[1][0][0][0][0]; wA1 = &g_wtc[1][1][0][0][0];
            emode = 1;
        } else {
            node = bz - NNODE;
            if (g_level[node] != round || g_nchild[node] == 0) return;
            in = g_chsum[node];
            wA0 = &g_wtc[3][0][0][0][0]; wA1 = &g_wtc[3][1][0][0][0];
            emode = 2;
        }
    } else {
        node = bz;
        if (g_level[node] != round || g_nchild[node] == 0) return;
        in = g_rh[node];
        wA0 = &g_wtc[5][0][0][0][0]; wA1 = &g_wtc[5][1][0][0][0];
        emode = 3;
    }

    extern __shared__ char dsm[];
    uint32_t sraw = smem_u32(dsm);
    uint32_t sbase = (sraw + 1023u) & ~1023u;
    char* sptr = dsm + (sbase - sraw);

    int tid = threadIdx.x;
    int lane = tid & 31, wid = tid >> 5;
    int wm = wid >> 2, wn = wid & 3;        // warp tile: M64 x N32
    int lr = lane & 7, lg = lane >> 3;

    int y0 = blockIdx.x * 2;
    int coBase = blockIdx.y * 128;
    int nch = (mode == 4) ? 8 : 72;

    int kcB = tid & 7;                       // B-build: 16B chunk within 64ch
    int nb0 = tid >> 3;                      // B-build: base pixel row (0..31)

    float acc[4][4][4];
#pragma unroll
    for (int a = 0; a < 4; ++a)
#pragma unroll
        for (int b = 0; b < 4; ++b)
#pragma unroll
            for (int c = 0; c < 4; ++c) acc[a][b][c] = 0.0f;

    // ---------- prologue: stage 0 ----------
    {
        int t = 0;
        int c0 = 0;
        int tb = (mode == 4) ? 4 : 0;
        int dy = tb / 3, dx = tb % 3;
        // A via cp.async
#pragma unroll
        for (int p = 0; p < 8; ++p) {
            int idx = (tid << 3) | p;
            int split = idx >> 10; int rem = idx & 1023;
            int o = rem >> 3; int kc = rem & 7;
            const __half* gsrc = (split ? wA1 : wA0) +
                (size_t)t * 262144 + (size_t)(coBase + o) * 512 + c0 + kc * 8;
            uint32_t sa = sbase + split * TILE_BYTES + o * 128 + ((kc ^ (o & 7)) << 4);
            cp_async16(sa, gsrc);
        }
        CP_COMMIT();
        // B synchronous
#pragma unroll
        for (int i = 0; i < 4; ++i) {
            int n = nb0 + 32 * i;
            int ry = n >> 6, x = n & 63;
            const float* gp = in + (size_t)((y0 + ry + dy) * PSTR + x + dx) * 512 + c0 + kcB * 8;
            float4 v0 = ((const float4*)gp)[0];
            float4 v1 = ((const float4*)gp)[1];
            uint4 uh, ul;
            cvt8(v0, v1, uh, ul);
            uint32_t off = (uint32_t)n * 128 + ((kcB ^ (n & 7)) << 4);
            *(uint4*)(sptr + 2 * TILE_BYTES + off) = uh;
            *(uint4*)(sptr + 3 * TILE_BYTES + off) = ul;
        }
        CP_WAIT0();
        __syncthreads();
    }

    // ---------- mainloop ----------
    for (int q = 0; q < nch; ++q) {
        int s = q & 1;
        uint32_t stAh = sbase + s * STAGE_BYTES;
        uint32_t stAl = stAh + TILE_BYTES;
        uint32_t stBh = stAh + 2 * TILE_BYTES;
        uint32_t stBl = stAh + 3 * TILE_BYTES;

        float4 pf[8];
        int dy2 = 0, dx2 = 0, c02 = 0, t2 = 0;
        bool more = (q + 1 < nch);
        if (more) {
            int qq = q + 1;
            t2 = (mode == 4) ? 0 : (qq >> 3);
            c02 = (qq & 7) << 6;
            int tb2 = (mode == 4) ? 4 : t2;
            dy2 = tb2 / 3; dx2 = tb2 % 3;
            // A cp.async into other stage
            uint32_t sb2 = sbase + (s ^ 1) * STAGE_BYTES;
#pragma unroll
            for (int p = 0; p < 8; ++p) {
                int idx = (tid << 3) | p;
                int split = idx >> 10; int rem = idx & 1023;
                int o = rem >> 3; int kc = rem & 7;
                const __half* gsrc = (split ? wA1 : wA0) +
                    (size_t)t2 * 262144 + (size_t)(coBase + o) * 512 + c02 + kc * 8;
                uint32_t sa = sb2 + split * TILE_BYTES + o * 128 + ((kc ^ (o & 7)) << 4);
                cp_async16(sa, gsrc);
            }
            CP_COMMIT();
            // B prefetch to regs
#pragma unroll
            for (int i = 0; i < 4; ++i) {
                int n = nb0 + 32 * i;
                int ry = n >> 6, x = n & 63;
                const float* gp = in + (size_t)((y0 + ry + dy2) * PSTR + x + dx2) * 512 + c02 + kcB * 8;
                pf[2 * i] = ((const float4*)gp)[0];
                pf[2 * i + 1] = ((const float4*)gp)[1];
            }
        }

        // ---- mma on stage s ----
#pragma unroll
        for (int ks = 0; ks < 4; ++ks) {
            int kc0 = ks * 2;
            uint32_t af[4][4], bhf[2][4], blf[2][4];
#pragma unroll
            for (int tm = 0; tm < 4; ++tm) {
                int row = wm * 64 + tm * 16 + lr + ((lg & 1) << 3);
                int ch = kc0 + (lg >> 1);
                ldsm_x4(af[tm], stAh + row * 128 + ((ch ^ (row & 7)) << 4));
            }
#pragma unroll
            for (int p = 0; p < 2; ++p) {
                int row = wn * 32 + p * 16 + lr + ((lg >> 1) << 3);
                int ch = kc0 + (lg & 1);
                uint32_t off = row * 128 + ((ch ^ (row & 7)) << 4);
                ldsm_x4(bhf[p], stBh + off);
                ldsm_x4(blf[p], stBl + off);
            }
#pragma unroll
            for (int tm = 0; tm < 4; ++tm)
#pragma unroll
                for (int tn = 0; tn < 4; ++tn) {
                    mma16816(acc[tm][tn], af[tm], &bhf[tn >> 1][(tn & 1) * 2]);
                    mma16816(acc[tm][tn], af[tm], &blf[tn >> 1][(tn & 1) * 2]);
                }
#pragma unroll
            for (int tm = 0; tm < 4; ++tm) {
                int row = wm * 64 + tm * 16 + lr + ((lg & 1) << 3);
                int ch = kc0 + (lg >> 1);
                ldsm_x4(af[tm], stAl + row * 128 + ((ch ^ (row & 7)) << 4));
            }
#pragma unroll
            for (int tm = 0; tm < 4; ++tm)
#pragma unroll
                for (int tn = 0; tn < 4; ++tn)
                    mma16816(acc[tm][tn], af[tm], &bhf[tn >> 1][(tn & 1) * 2]);
        }

        if (more) {
            char* so = sptr + (s ^ 1) * STAGE_BYTES;
#pragma unroll
            for (int i = 0; i < 4; ++i) {
                int n = nb0 + 32 * i;
                uint4 uh, ul;
                cvt8(pf[2 * i], pf[2 * i + 1], uh, ul);
                uint32_t off = (uint32_t)n * 128 + ((kcB ^ (n & 7)) << 4);
                *(uint4*)(so + 2 * TILE_BYTES + off) = uh;
                *(uint4*)(so + 3 * TILE_BYTES + off) = ul;
            }
        }
        CP_WAIT0();
        __syncthreads();
    }

    // ---------- epilogue ----------
#pragma unroll
    for (int tm = 0; tm < 4; ++tm) {
#pragma unroll
        for (int tn = 0; tn < 4; ++tn) {
#pragma unroll
            for (int j = 0; j < 4; ++j) {
                int m = wm * 64 + tm * 16 + (lane >> 2) + ((j >> 1) << 3);
                int n = wn * 32 + tn * 8 + ((lane & 3) << 1) + (j & 1);
                int o = coBase + m;
                int ry = n >> 6, x = n & 63;
                int y = y0 + ry;
                size_t pidx = (size_t)((y + 1) * PSTR + x + 1) * 512 + o;
                float v = acc[tm][tn][j];
                if (emode == 4) {
                    g_V1[pidx] = v;
                } else if (emode == 0) {
                    g_A[outsel][pidx] = v;
                } else {
                    int yt = (y == 0) ? 0 : ((y == 63) ? 2 : 1);
                    int xt = (x == 0) ? 0 : ((x == 63) ? 2 : 1);
                    int cls = yt * 3 + xt;
                    if (emode == 1) {
                        float r = sigm(v + g_A[0][pidx] + g_bmap[0][node][cls * CH + o]);
                        atomicAdd(&g_rh[node][pidx], r * in[pidx]);
                    } else if (emode == 2) {
                        g_z[node][pidx] = sigm(v + g_A[1][pidx] + g_bmap[1][node][cls * CH + o]);
                    } else {
                        float ri = tanhf(v + g_A[2][pidx] + g_bmap[2][node][cls * CH + o]);
                        float zz = g_z[node][pidx];
                        g_h[node][pidx] = (1.0f - zz) * ri + zz * g_chsum[node][pidx];
                    }
                }
            }
        }
    }
}

// ======================= ch_sum + zero rh =======================
__global__ void k_chsum(int round) {
    int n = blockIdx.y;
    if (g_level[n] != round || g_nchild[n] == 0) return;
    int nc = g_nchild[n];
    size_t base = (size_t)blockIdx.x * 2048 + threadIdx.x;
#pragma unroll
    for (int e = 0; e < 8; ++e) {
        size_t i = base + (size_t)e * 256;
        float s = 0.0f;
        for (int ci = 0; ci < nc; ++ci) s += g_h[g_child[n][ci]][i];
        g_chsum[n][i] = s;
        g_rh[n][i] = 0.0f;
    }
}

// ======================= leaves =======================
__global__ void k_leaf() {
    int n = blockIdx.y;
    if (g_nchild[n] != 0) return;
    size_t base = (size_t)blockIdx.x * 2048 + threadIdx.x;
#pragma unroll
    for (int e = 0; e < 8; ++e) {
        size_t i = base + (size_t)e * 256;
        int c = (int)(i & 511);
        int pp = (int)(i >> 9);
        int y = pp / PSTR - 1, x = pp % PSTR - 1;
        float hv = 0.0f;
        if ((unsigned)y < 64u && (unsigned)x < 64u) {
            int yt = (y == 0) ? 0 : ((y == 63) ? 2 : 1);
            int xt = (x == 0) ? 0 : ((x == 63) ? 2 : 1);
            int cls = yt * 3 + xt;
            float zu = sigm(g_A[1][i] + g_bmap[1][n][cls * CH + c]);
            float ro = tanhf(g_A[2][i] + g_bmap[2][n][cls * CH + c]);
            hv = (1.0f - zu) * ro;
        }
        g_h[n][i] = hv;
    }
}

// ======================= output: padded NHWC -> NCHW =======================
__global__ __launch_bounds__(256) void k_copyout(float* out) {
    __shared__ float sm[64][129];
    int root = g_root;
    int y = blockIdx.x; int oc = blockIdx.y;
    const float* src = g_h[root] + (size_t)((y + 1) * PSTR + 1) * 512 + oc * 128;
    for (int i = threadIdx.x; i < 64 * 128; i += 256) {
        int x = i >> 7, o = i & 127;
        sm[x][o] = src[(size_t)x * 512 + o];
    }
    __syncthreads();
    for (int i = threadIdx.x; i < 64 * 128; i += 256) {
        int o = i >> 6, x = i & 63;
        out[(size_t)(oc * 128 + o) * 4096 + y * 64 + x] = sm[x][o];
    }
}

// ======================= launch =======================
extern "C" void kernel_launch(void* const* d_in, const int* in_sizes, int n_in,
                              void* d_out, int out_size) {
    const float* vis  = (const float*)d_in[0];
    const float* lang = (const float*)d_in[1];
    const int*   adj  = (const int*)d_in[2];
    const float* mw   = (const float*)d_in[3];
    const float* mb   = (const float*)d_in[4];
    const float* rw   = (const float*)d_in[5];
    const float* rb   = (const float*)d_in[6];
    const float* uw   = (const float*)d_in[7];
    const float* ub   = (const float*)d_in[8];
    const float* ow   = (const float*)d_in[9];
    const float* ob   = (const float*)d_in[10];
    float* out = (float*)d_out;

    cudaFuncSetAttribute(k_conv, cudaFuncAttributeMaxDynamicSharedMemorySize, CONV_SMEM);

    k_prep<<<1, 1>>>(adj);
    k_zero<<<dim3(520, 85), 256>>>();
    k_tvis<<<dim3(64, 4), 256>>>(vis);
    {
        size_t tot = (size_t)6 * 9 * 512 * 512 + (size_t)512 * 512;
        k_packtc<<<(unsigned)((tot + 255) / 256), 256>>>(rw, uw, ow, mw);
    }
    k_wsum<<<(3 * CH * CH) / 256, 256>>>(rw, uw, ow);
    k_lb<<<NNODE, CH>>>(lang, mw, mb);
    k_bmap<<<dim3(2, 27), 256>>>(rb, ub, ob);

    k_conv<<<dim3(32, 4, 1), 256, CONV_SMEM>>>(4, 0);   // V1
    k_conv<<<dim3(32, 4, 3), 256, CONV_SMEM>>>(0, 0);   // A_r, A_u, A_o
    k_leaf<<<dim3(1089, NNODE), 256>>>();

    for (int t = 1; t <= MAXROUND; ++t) {
        k_chsum<<<dim3(1089, NNODE), 256>>>(t);
        k_conv<<<dim3(32, 4, 2 * NNODE), 256, CONV_SMEM>>>(12, t);  // reset + update
        k_conv<<<dim3(32, 4, NNODE), 256, CONV_SMEM>>>(3, t);       // output
    }
    k_copyout<<<dim3(64, 4), 256>>>(out);
}